// round 1
// baseline (speedup 1.0000x reference)
#include <cuda_runtime.h>

// Problem constants (fixed by the reference)
#define NB 8
#define CC 3
#define HD 1024
#define WD 1280
#define HS 800
#define WS 1280

__global__ void __launch_bounds__(256)
warp_from_depth_kernel(const float* __restrict__ depth,
                       const float* __restrict__ src,
                       const float* __restrict__ abc,
                       const float* __restrict__ tr,
                       const float* __restrict__ pi,
                       float* __restrict__ out)
{
    int idx = blockIdx.x * blockDim.x + threadIdx.x;
    const int HW = HD * WD;
    if (idx >= NB * HW) return;

    int n  = idx / HW;
    int hw = idx - n * HW;

    float d = depth[idx];
    float a = __ldg(abc + hw);
    float b = __ldg(abc + HW + hw);
    float c = __ldg(abc + 2 * HW + hw);

    float tx = __ldg(tr + 0), ty = __ldg(tr + 1), tz = __ldg(tr + 2);
    float fu = __ldg(pi + 0), fv = __ldg(pi + 1);
    float du = __ldg(pi + 2), dv = __ldg(pi + 3);

    float denom = fmaf(c, d, tz);
    float inv   = 1.0f / denom;
    float xx = fmaf(a, d, tx) * inv;
    float yy = fmaf(b, d, ty) * inv;
    float uu = fmaf(fu, xx, du);
    float vv = fmaf(fv, yy, dv);

    // Replicate reference normalization + unnormalization literally
    float gx = 2.0f * uu * (1.0f / (float)(WS - 1)) - 1.0f;
    float gy = 2.0f * vv * (1.0f / (float)(HS - 1)) - 1.0f;
    float x = ((gx + 1.0f) * (float)WS - 1.0f) * 0.5f;
    float y = ((gy + 1.0f) * (float)HS - 1.0f) * 0.5f;

    x = fminf(fmaxf(x, 0.0f), (float)(WS - 1));
    y = fminf(fmaxf(y, 0.0f), (float)(HS - 1));

    float x0f = floorf(x), y0f = floorf(y);
    float wx = x - x0f,    wy = y - y0f;
    int x0 = (int)x0f, y0 = (int)y0f;
    int dx = (x0 < WS - 1) ? 1  : 0;
    int dy = (y0 < HS - 1) ? WS : 0;

    int p = y0 * WS + x0;
    float w00 = (1.0f - wy) * (1.0f - wx);
    float w01 = (1.0f - wy) * wx;
    float w10 = wy * (1.0f - wx);
    float w11 = wy * wx;

    const float* s0 = src + (long)n * CC * HS * WS;
    float* o0 = out + (long)n * CC * HW + hw;

#pragma unroll
    for (int ch = 0; ch < CC; ch++) {
        const float* s = s0 + ch * HS * WS;
        float v = __ldg(s + p)           * w00
                + __ldg(s + p + dx)      * w01
                + __ldg(s + p + dy)      * w10
                + __ldg(s + p + dy + dx) * w11;
        o0[ch * HW] = v;
    }
}

extern "C" void kernel_launch(void* const* d_in, const int* in_sizes, int n_in,
                              void* d_out, int out_size)
{
    const float* depth = (const float*)d_in[0];
    const float* src   = (const float*)d_in[1];
    const float* abc   = (const float*)d_in[2];
    const float* tr    = (const float*)d_in[3];
    const float* pi    = (const float*)d_in[4];
    float* out = (float*)d_out;

    int total = NB * HD * WD;
    int threads = 256;
    int blocks = (total + threads - 1) / threads;
    warp_from_depth_kernel<<<blocks, threads>>>(depth, src, abc, tr, pi, out);
}